// round 8
// baseline (speedup 1.0000x reference)
#include <cuda_runtime.h>
#include <cuda_bf16.h>

// Problem constants
#define B_DIM 8
#define N_DIM 1024
#define C_DIM 1024
#define H_DIM 16
#define HD    64

// Scratch (static __device__ arrays: allocation-free per harness rules)
__device__ float g_qkv[(size_t)B_DIM * N_DIM * 3 * C_DIM];        // 96 MiB
__device__ float g_ctx[(size_t)B_DIM * N_DIM * C_DIM];            // 32 MiB
__device__ float g_attn[(size_t)B_DIM * H_DIM * N_DIM * N_DIM];   // 512 MiB (fallback if attn not in d_out)

// ---------------------------------------------------------------------------
// Generic tiled SGEMM: C = alpha * A @ op(B) (+ bias), batched via blockIdx.z
// A row-major [M,K] (lda), B row-major; TRANSB=false: B is [K,N] (ldb),
// TRANSB=true: B is [N,K] (ldb) and we compute A @ B^T.
// Batch offset = (z / innerCount) * s?o + (z % innerCount) * s?i.
// All dims assumed multiples of tile sizes (true for this problem).
// ---------------------------------------------------------------------------
template <int BM, int BN, int BK, int TM, int TN, bool TRANSB>
__global__ void __launch_bounds__((BM / TM) * (BN / TN))
sgemm_k(const float* __restrict__ A, const float* __restrict__ B,
        float* __restrict__ C, const float* __restrict__ bias,
        int K, int lda, int ldb, int ldc,
        long sAi, long sAo, long sBi, long sBo, long sCi, long sCo,
        int innerCount, float alpha)
{
    constexpr int THREADS = (BM / TM) * (BN / TN);
    __shared__ float As[BK][BM];
    __shared__ float Bs[BK][BN];

    const int z  = blockIdx.z;
    const int zo = z / innerCount;
    const int zi = z % innerCount;
    A += (long)zo * sAo + (long)zi * sAi;
    B += (long)zo * sBo + (long)zi * sBi;
    C += (long)zo * sCo + (long)zi * sCi;

    const int m0  = blockIdx.y * BM;
    const int n0  = blockIdx.x * BN;
    const int tid = threadIdx.x;
    const int tx  = tid % (BN / TN);
    const int ty  = tid / (BN / TN);

    float acc[TM][TN];
#pragma unroll
    for (int i = 0; i < TM; i++)
#pragma unroll
        for (int j = 0; j < TN; j++) acc[i][j] = 0.0f;

    for (int k0 = 0; k0 < K; k0 += BK) {
        // ---- load A tile [BM x BK] as float4 along K, store transposed ----
        constexpr int A_F4 = BM * BK / 4;
#pragma unroll
        for (int it = 0; it < A_F4 / THREADS; it++) {
            int i   = tid + it * THREADS;
            int row = i / (BK / 4);
            int c4  = i % (BK / 4);
            float4 v = *reinterpret_cast<const float4*>(
                &A[(long)(m0 + row) * lda + k0 + c4 * 4]);
            As[c4 * 4 + 0][row] = v.x;
            As[c4 * 4 + 1][row] = v.y;
            As[c4 * 4 + 2][row] = v.z;
            As[c4 * 4 + 3][row] = v.w;
        }
        // ---- load B tile [BK x BN] ----
        constexpr int B_F4 = BK * BN / 4;
        if (!TRANSB) {
#pragma unroll
            for (int it = 0; it < B_F4 / THREADS; it++) {
                int i   = tid + it * THREADS;
                int row = i / (BN / 4);
                int c4  = i % (BN / 4);
                float4 v = *reinterpret_cast<const float4*>(
                    &B[(long)(k0 + row) * ldb + n0 + c4 * 4]);
                *reinterpret_cast<float4*>(&Bs[row][c4 * 4]) = v;
            }
        } else {
#pragma unroll
            for (int it = 0; it < B_F4 / THREADS; it++) {
                int i  = tid + it * THREADS;
                int n  = i / (BK / 4);
                int k4 = i % (BK / 4);
                float4 v = *reinterpret_cast<const float4*>(
                    &B[(long)(n0 + n) * ldb + k0 + k4 * 4]);
                Bs[k4 * 4 + 0][n] = v.x;
                Bs[k4 * 4 + 1][n] = v.y;
                Bs[k4 * 4 + 2][n] = v.z;
                Bs[k4 * 4 + 3][n] = v.w;
            }
        }
        __syncthreads();

        // ---- compute ----
#pragma unroll
        for (int kk = 0; kk < BK; kk++) {
            float ra[TM], rb[TN];
#pragma unroll
            for (int i = 0; i < TM; i += 4) {
                float4 t = *reinterpret_cast<const float4*>(&As[kk][ty * TM + i]);
                ra[i] = t.x; ra[i + 1] = t.y; ra[i + 2] = t.z; ra[i + 3] = t.w;
            }
#pragma unroll
            for (int j = 0; j < TN; j += 4) {
                float4 t = *reinterpret_cast<const float4*>(&Bs[kk][tx * TN + j]);
                rb[j] = t.x; rb[j + 1] = t.y; rb[j + 2] = t.z; rb[j + 3] = t.w;
            }
#pragma unroll
            for (int i = 0; i < TM; i++)
#pragma unroll
                for (int j = 0; j < TN; j++)
                    acc[i][j] = fmaf(ra[i], rb[j], acc[i][j]);
        }
        __syncthreads();
    }

    // ---- epilogue ----
#pragma unroll
    for (int i = 0; i < TM; i++) {
#pragma unroll
        for (int j = 0; j < TN; j += 4) {
            float4 v;
            v.x = alpha * acc[i][j + 0];
            v.y = alpha * acc[i][j + 1];
            v.z = alpha * acc[i][j + 2];
            v.w = alpha * acc[i][j + 3];
            if (bias != nullptr) {
                int nb = n0 + tx * TN + j;
                v.x += bias[nb + 0];
                v.y += bias[nb + 1];
                v.z += bias[nb + 2];
                v.w += bias[nb + 3];
            }
            *reinterpret_cast<float4*>(
                &C[(long)(m0 + ty * TM + i) * ldc + n0 + tx * TN + j]) = v;
        }
    }
}

// ---------------------------------------------------------------------------
// Row softmax over rows of exactly 1024 floats. One 256-thread block per row;
// each thread owns one float4 in registers (single read, single write).
// ---------------------------------------------------------------------------
__global__ void softmax1024(float* __restrict__ data)
{
    const long row = blockIdx.x;
    float4* p = reinterpret_cast<float4*>(data + row * 1024);
    const int t    = threadIdx.x;
    const int warp = t >> 5;
    const int lane = t & 31;

    float4 v = p[t];
    float m = fmaxf(fmaxf(v.x, v.y), fmaxf(v.z, v.w));
#pragma unroll
    for (int o = 16; o > 0; o >>= 1)
        m = fmaxf(m, __shfl_xor_sync(0xffffffffu, m, o));

    __shared__ float red[8];
    if (lane == 0) red[warp] = m;
    __syncthreads();
    float M = red[0];
#pragma unroll
    for (int i = 1; i < 8; i++) M = fmaxf(M, red[i]);

    v.x = expf(v.x - M);
    v.y = expf(v.y - M);
    v.z = expf(v.z - M);
    v.w = expf(v.w - M);
    float s = v.x + v.y + v.z + v.w;
#pragma unroll
    for (int o = 16; o > 0; o >>= 1)
        s += __shfl_xor_sync(0xffffffffu, s, o);

    __syncthreads();  // red reuse
    if (lane == 0) red[warp] = s;
    __syncthreads();
    float S = red[0];
#pragma unroll
    for (int i = 1; i < 8; i++) S += red[i];

    const float r = 1.0f / S;
    v.x *= r; v.y *= r; v.z *= r; v.w *= r;
    p[t] = v;
}

// ---------------------------------------------------------------------------
// kernel_launch
// ---------------------------------------------------------------------------
extern "C" void kernel_launch(void* const* d_in, const int* in_sizes, int n_in,
                              void* d_out, int out_size)
{
    const float* x      = (const float*)d_in[0];
    const float* w_qkv  = (const float*)d_in[1];
    const float* w_proj = (const float*)d_in[2];
    const float* b_proj = (const float*)d_in[3];
    float* out = (float*)d_out;

    float *qkv, *ctx, *attn_scratch;
    cudaGetSymbolAddress((void**)&qkv, g_qkv);
    cudaGetSymbolAddress((void**)&ctx, g_ctx);
    cudaGetSymbolAddress((void**)&attn_scratch, g_attn);

    const long OUT_ELEMS  = (long)B_DIM * N_DIM * C_DIM;                 // 8388608
    const long ATTN_ELEMS = (long)B_DIM * H_DIM * N_DIM * N_DIM;        // 134217728
    // Reference returns (out, attn): if the harness buffer holds both, write
    // attn straight into it; otherwise keep it in scratch (still needed for ctx).
    float* attn = ((long)out_size >= OUT_ELEMS + ATTN_ELEMS) ? (out + OUT_ELEMS)
                                                             : attn_scratch;

    // 1) qkv = x @ w_qkv                  [8192,3072] = [8192,1024] @ [1024,3072]
    {
        dim3 grid(3 * C_DIM / 128, (B_DIM * N_DIM) / 128, 1);
        sgemm_k<128, 128, 16, 8, 8, false><<<grid, 256>>>(
            x, w_qkv, qkv, nullptr,
            C_DIM, C_DIM, 3 * C_DIM, 3 * C_DIM,
            0, 0, 0, 0, 0, 0, 1, 1.0f);
    }

    // 2) scores = scale * Q @ K^T  per (b,h): [1024,1024] = [1024,64] @ [64,1024]
    {
        dim3 grid(N_DIM / 128, N_DIM / 128, B_DIM * H_DIM);
        sgemm_k<128, 128, 16, 8, 8, true><<<grid, 256>>>(
            qkv /*Q*/, qkv + C_DIM /*K*/, attn, nullptr,
            HD, 3 * C_DIM, 3 * C_DIM, N_DIM,
            /*Q:*/ (long)HD, (long)N_DIM * 3 * C_DIM,
            /*K:*/ (long)HD, (long)N_DIM * 3 * C_DIM,
            /*S:*/ (long)N_DIM * N_DIM, (long)H_DIM * N_DIM * N_DIM,
            H_DIM, 0.125f /* hd^-0.5 */);
    }

    // 3) softmax over keys (rows of 1024)
    softmax1024<<<B_DIM * H_DIM * N_DIM, 256>>>(attn);

    // 4) ctx = attn @ V  per (b,h): [1024,64] = [1024,1024] @ [1024,64]
    {
        dim3 grid(HD / 64, N_DIM / 128, B_DIM * H_DIM);
        sgemm_k<128, 64, 16, 8, 4, false><<<grid, 256>>>(
            attn, qkv + 2 * C_DIM /*V*/, ctx, nullptr,
            N_DIM, N_DIM, 3 * C_DIM, C_DIM,
            /*A:*/ (long)N_DIM * N_DIM, (long)H_DIM * N_DIM * N_DIM,
            /*V:*/ (long)HD, (long)N_DIM * 3 * C_DIM,
            /*C:*/ (long)HD, (long)N_DIM * C_DIM,
            H_DIM, 1.0f);
    }

    // 5) out = ctx @ w_proj + b_proj      [8192,1024] = [8192,1024] @ [1024,1024]
    {
        dim3 grid(C_DIM / 128, (B_DIM * N_DIM) / 128, 1);
        sgemm_k<128, 128, 16, 8, 8, false><<<grid, 256>>>(
            ctx, w_proj, out, b_proj,
            C_DIM, C_DIM, C_DIM, C_DIM,
            0, 0, 0, 0, 0, 0, 1, 1.0f);
    }
}

// round 9
// speedup vs baseline: 1.0020x; 1.0020x over previous
#include <cuda_runtime.h>
#include <cuda_bf16.h>

// Problem constants
#define B_DIM 8
#define N_DIM 1024
#define C_DIM 1024
#define H_DIM 16
#define HD    64

// Scratch (static __device__ arrays: allocation-free per harness rules)
__device__ float g_qkv[(size_t)B_DIM * N_DIM * 3 * C_DIM];        // 96 MiB
__device__ float g_ctx[(size_t)B_DIM * N_DIM * C_DIM];            // 32 MiB
__device__ float g_attn[(size_t)B_DIM * H_DIM * N_DIM * N_DIM];   // 512 MiB (fallback if attn not in d_out)

// ---------------------------------------------------------------------------
// Generic tiled SGEMM: C = alpha * A @ op(B) (+ bias), batched via blockIdx.z
// A row-major [M,K] (lda), B row-major; TRANSB=false: B is [K,N] (ldb),
// TRANSB=true: B is [N,K] (ldb) and we compute A @ B^T.
// Batch offset = (z / innerCount) * s?o + (z % innerCount) * s?i.
// All dims assumed multiples of tile sizes (true for this problem).
// ---------------------------------------------------------------------------
template <int BM, int BN, int BK, int TM, int TN, bool TRANSB>
__global__ void __launch_bounds__((BM / TM) * (BN / TN))
sgemm_k(const float* __restrict__ A, const float* __restrict__ B,
        float* __restrict__ C, const float* __restrict__ bias,
        int K, int lda, int ldb, int ldc,
        long sAi, long sAo, long sBi, long sBo, long sCi, long sCo,
        int innerCount, float alpha)
{
    constexpr int THREADS = (BM / TM) * (BN / TN);
    __shared__ float As[BK][BM];
    __shared__ float Bs[BK][BN];

    const int z  = blockIdx.z;
    const int zo = z / innerCount;
    const int zi = z % innerCount;
    A += (long)zo * sAo + (long)zi * sAi;
    B += (long)zo * sBo + (long)zi * sBi;
    C += (long)zo * sCo + (long)zi * sCi;

    const int m0  = blockIdx.y * BM;
    const int n0  = blockIdx.x * BN;
    const int tid = threadIdx.x;
    const int tx  = tid % (BN / TN);
    const int ty  = tid / (BN / TN);

    float acc[TM][TN];
#pragma unroll
    for (int i = 0; i < TM; i++)
#pragma unroll
        for (int j = 0; j < TN; j++) acc[i][j] = 0.0f;

    for (int k0 = 0; k0 < K; k0 += BK) {
        // ---- load A tile [BM x BK] as float4 along K, store transposed ----
        constexpr int A_F4 = BM * BK / 4;
#pragma unroll
        for (int it = 0; it < A_F4 / THREADS; it++) {
            int i   = tid + it * THREADS;
            int row = i / (BK / 4);
            int c4  = i % (BK / 4);
            float4 v = *reinterpret_cast<const float4*>(
                &A[(long)(m0 + row) * lda + k0 + c4 * 4]);
            As[c4 * 4 + 0][row] = v.x;
            As[c4 * 4 + 1][row] = v.y;
            As[c4 * 4 + 2][row] = v.z;
            As[c4 * 4 + 3][row] = v.w;
        }
        // ---- load B tile [BK x BN] ----
        constexpr int B_F4 = BK * BN / 4;
        if (!TRANSB) {
#pragma unroll
            for (int it = 0; it < B_F4 / THREADS; it++) {
                int i   = tid + it * THREADS;
                int row = i / (BN / 4);
                int c4  = i % (BN / 4);
                float4 v = *reinterpret_cast<const float4*>(
                    &B[(long)(k0 + row) * ldb + n0 + c4 * 4]);
                *reinterpret_cast<float4*>(&Bs[row][c4 * 4]) = v;
            }
        } else {
#pragma unroll
            for (int it = 0; it < B_F4 / THREADS; it++) {
                int i  = tid + it * THREADS;
                int n  = i / (BK / 4);
                int k4 = i % (BK / 4);
                float4 v = *reinterpret_cast<const float4*>(
                    &B[(long)(n0 + n) * ldb + k0 + k4 * 4]);
                Bs[k4 * 4 + 0][n] = v.x;
                Bs[k4 * 4 + 1][n] = v.y;
                Bs[k4 * 4 + 2][n] = v.z;
                Bs[k4 * 4 + 3][n] = v.w;
            }
        }
        __syncthreads();

        // ---- compute ----
#pragma unroll
        for (int kk = 0; kk < BK; kk++) {
            float ra[TM], rb[TN];
#pragma unroll
            for (int i = 0; i < TM; i += 4) {
                float4 t = *reinterpret_cast<const float4*>(&As[kk][ty * TM + i]);
                ra[i] = t.x; ra[i + 1] = t.y; ra[i + 2] = t.z; ra[i + 3] = t.w;
            }
#pragma unroll
            for (int j = 0; j < TN; j += 4) {
                float4 t = *reinterpret_cast<const float4*>(&Bs[kk][tx * TN + j]);
                rb[j] = t.x; rb[j + 1] = t.y; rb[j + 2] = t.z; rb[j + 3] = t.w;
            }
#pragma unroll
            for (int i = 0; i < TM; i++)
#pragma unroll
                for (int j = 0; j < TN; j++)
                    acc[i][j] = fmaf(ra[i], rb[j], acc[i][j]);
        }
        __syncthreads();
    }

    // ---- epilogue ----
#pragma unroll
    for (int i = 0; i < TM; i++) {
#pragma unroll
        for (int j = 0; j < TN; j += 4) {
            float4 v;
            v.x = alpha * acc[i][j + 0];
            v.y = alpha * acc[i][j + 1];
            v.z = alpha * acc[i][j + 2];
            v.w = alpha * acc[i][j + 3];
            if (bias != nullptr) {
                int nb = n0 + tx * TN + j;
                v.x += bias[nb + 0];
                v.y += bias[nb + 1];
                v.z += bias[nb + 2];
                v.w += bias[nb + 3];
            }
            *reinterpret_cast<float4*>(
                &C[(long)(m0 + ty * TM + i) * ldc + n0 + tx * TN + j]) = v;
        }
    }
}

// ---------------------------------------------------------------------------
// Row softmax over rows of exactly 1024 floats. One 256-thread block per row;
// each thread owns one float4 in registers (single read, single write).
// ---------------------------------------------------------------------------
__global__ void softmax1024(float* __restrict__ data)
{
    const long row = blockIdx.x;
    float4* p = reinterpret_cast<float4*>(data + row * 1024);
    const int t    = threadIdx.x;
    const int warp = t >> 5;
    const int lane = t & 31;

    float4 v = p[t];
    float m = fmaxf(fmaxf(v.x, v.y), fmaxf(v.z, v.w));
#pragma unroll
    for (int o = 16; o > 0; o >>= 1)
        m = fmaxf(m, __shfl_xor_sync(0xffffffffu, m, o));

    __shared__ float red[8];
    if (lane == 0) red[warp] = m;
    __syncthreads();
    float M = red[0];
#pragma unroll
    for (int i = 1; i < 8; i++) M = fmaxf(M, red[i]);

    v.x = expf(v.x - M);
    v.y = expf(v.y - M);
    v.z = expf(v.z - M);
    v.w = expf(v.w - M);
    float s = v.x + v.y + v.z + v.w;
#pragma unroll
    for (int o = 16; o > 0; o >>= 1)
        s += __shfl_xor_sync(0xffffffffu, s, o);

    __syncthreads();  // red reuse
    if (lane == 0) red[warp] = s;
    __syncthreads();
    float S = red[0];
#pragma unroll
    for (int i = 1; i < 8; i++) S += red[i];

    const float r = 1.0f / S;
    v.x *= r; v.y *= r; v.z *= r; v.w *= r;
    p[t] = v;
}

// ---------------------------------------------------------------------------
// kernel_launch
// ---------------------------------------------------------------------------
extern "C" void kernel_launch(void* const* d_in, const int* in_sizes, int n_in,
                              void* d_out, int out_size)
{
    const float* x      = (const float*)d_in[0];
    const float* w_qkv  = (const float*)d_in[1];
    const float* w_proj = (const float*)d_in[2];
    const float* b_proj = (const float*)d_in[3];
    float* out = (float*)d_out;

    float *qkv, *ctx, *attn_scratch;
    cudaGetSymbolAddress((void**)&qkv, g_qkv);
    cudaGetSymbolAddress((void**)&ctx, g_ctx);
    cudaGetSymbolAddress((void**)&attn_scratch, g_attn);

    const long OUT_ELEMS  = (long)B_DIM * N_DIM * C_DIM;                 // 8388608
    const long ATTN_ELEMS = (long)B_DIM * H_DIM * N_DIM * N_DIM;        // 134217728
    // Reference returns (out, attn): if the harness buffer holds both, write
    // attn straight into it; otherwise keep it in scratch (still needed for ctx).
    float* attn = ((long)out_size >= OUT_ELEMS + ATTN_ELEMS) ? (out + OUT_ELEMS)
                                                             : attn_scratch;

    // 1) qkv = x @ w_qkv                  [8192,3072] = [8192,1024] @ [1024,3072]
    {
        dim3 grid(3 * C_DIM / 128, (B_DIM * N_DIM) / 128, 1);
        sgemm_k<128, 128, 16, 8, 8, false><<<grid, 256>>>(
            x, w_qkv, qkv, nullptr,
            C_DIM, C_DIM, 3 * C_DIM, 3 * C_DIM,
            0, 0, 0, 0, 0, 0, 1, 1.0f);
    }

    // 2) scores = scale * Q @ K^T  per (b,h): [1024,1024] = [1024,64] @ [64,1024]
    {
        dim3 grid(N_DIM / 128, N_DIM / 128, B_DIM * H_DIM);
        sgemm_k<128, 128, 16, 8, 8, true><<<grid, 256>>>(
            qkv /*Q*/, qkv + C_DIM /*K*/, attn, nullptr,
            HD, 3 * C_DIM, 3 * C_DIM, N_DIM,
            /*Q:*/ (long)HD, (long)N_DIM * 3 * C_DIM,
            /*K:*/ (long)HD, (long)N_DIM * 3 * C_DIM,
            /*S:*/ (long)N_DIM * N_DIM, (long)H_DIM * N_DIM * N_DIM,
            H_DIM, 0.125f /* hd^-0.5 */);
    }

    // 3) softmax over keys (rows of 1024)
    softmax1024<<<B_DIM * H_DIM * N_DIM, 256>>>(attn);

    // 4) ctx = attn @ V  per (b,h): [1024,64] = [1024,1024] @ [1024,64]
    {
        dim3 grid(HD / 64, N_DIM / 128, B_DIM * H_DIM);
        sgemm_k<128, 64, 16, 8, 4, false><<<grid, 256>>>(
            attn, qkv + 2 * C_DIM /*V*/, ctx, nullptr,
            N_DIM, N_DIM, 3 * C_DIM, C_DIM,
            /*A:*/ (long)N_DIM * N_DIM, (long)H_DIM * N_DIM * N_DIM,
            /*V:*/ (long)HD, (long)N_DIM * 3 * C_DIM,
            /*C:*/ (long)HD, (long)N_DIM * C_DIM,
            H_DIM, 1.0f);
    }

    // 5) out = ctx @ w_proj + b_proj      [8192,1024] = [8192,1024] @ [1024,1024]
    {
        dim3 grid(C_DIM / 128, (B_DIM * N_DIM) / 128, 1);
        sgemm_k<128, 128, 16, 8, 8, false><<<grid, 256>>>(
            ctx, w_proj, out, b_proj,
            C_DIM, C_DIM, C_DIM, C_DIM,
            0, 0, 0, 0, 0, 0, 1, 1.0f);
    }
}

// round 13
// speedup vs baseline: 1.8196x; 1.8160x over previous
#include <cuda_runtime.h>
#include <cuda_bf16.h>
#include <cstdint>

#define B_DIM 8
#define N_DIM 1024
#define C_DIM 1024
#define H_DIM 16
#define HD    64

// ---------------------------------------------------------------------------
// Static device scratch (allocation-free per harness rules)
// ---------------------------------------------------------------------------
__device__ __nv_bfloat16 g_x_hi   [(size_t)B_DIM * N_DIM * C_DIM];       // 16MB
__device__ __nv_bfloat16 g_x_lo   [(size_t)B_DIM * N_DIM * C_DIM];
__device__ __nv_bfloat16 g_wqkvT_hi[(size_t)3 * C_DIM * C_DIM];          // 6MB
__device__ __nv_bfloat16 g_wqkvT_lo[(size_t)3 * C_DIM * C_DIM];
__device__ __nv_bfloat16 g_wprojT_hi[(size_t)C_DIM * C_DIM];             // 2MB
__device__ __nv_bfloat16 g_wprojT_lo[(size_t)C_DIM * C_DIM];
__device__ __nv_bfloat16 g_qkv_hi [(size_t)B_DIM * N_DIM * 3 * C_DIM];  // 48MB
__device__ __nv_bfloat16 g_qkv_lo [(size_t)B_DIM * N_DIM * 3 * C_DIM];
__device__ __nv_bfloat16 g_vT_hi  [(size_t)B_DIM * H_DIM * HD * N_DIM]; // 16MB
__device__ __nv_bfloat16 g_vT_lo  [(size_t)B_DIM * H_DIM * HD * N_DIM];
__device__ float         g_attn   [(size_t)B_DIM * H_DIM * N_DIM * N_DIM]; // 512MB
__device__ __nv_bfloat16 g_attn_hi[(size_t)B_DIM * H_DIM * N_DIM * N_DIM]; // 256MB
__device__ __nv_bfloat16 g_attn_lo[(size_t)B_DIM * H_DIM * N_DIM * N_DIM]; // 256MB
__device__ __nv_bfloat16 g_ctx_hi [(size_t)B_DIM * N_DIM * C_DIM];      // 16MB
__device__ __nv_bfloat16 g_ctx_lo [(size_t)B_DIM * N_DIM * C_DIM];

// ---------------------------------------------------------------------------
// PTX helpers
// ---------------------------------------------------------------------------
__device__ __forceinline__ uint32_t smem_u32(const void* p) {
    return (uint32_t)__cvta_generic_to_shared(p);
}
__device__ __forceinline__ void ldsm_x4(uint32_t r[4], uint32_t addr) {
    asm volatile("ldmatrix.sync.aligned.m8n8.x4.shared.b16 {%0,%1,%2,%3}, [%4];"
                 : "=r"(r[0]), "=r"(r[1]), "=r"(r[2]), "=r"(r[3]) : "r"(addr));
}
__device__ __forceinline__ void mma16816(float c[4], const uint32_t a[4],
                                         const uint32_t b[2]) {
    asm volatile(
        "mma.sync.aligned.m16n8k16.row.col.f32.bf16.bf16.f32 "
        "{%0,%1,%2,%3}, {%4,%5,%6,%7}, {%8,%9}, {%0,%1,%2,%3};"
        : "+f"(c[0]), "+f"(c[1]), "+f"(c[2]), "+f"(c[3])
        : "r"(a[0]), "r"(a[1]), "r"(a[2]), "r"(a[3]), "r"(b[0]), "r"(b[1]));
}
__device__ __forceinline__ void cp16(void* s, const void* g) {
    asm volatile("cp.async.cg.shared.global [%0], [%1], 16;"
                 :: "r"(smem_u32(s)), "l"(g));
}
#define CP_COMMIT asm volatile("cp.async.commit_group;")
#define CP_WAIT0  asm volatile("cp.async.wait_group 0;")

__device__ __forceinline__ void split2(float v, __nv_bfloat16& h, __nv_bfloat16& l) {
    h = __float2bfloat16(v);
    l = __float2bfloat16(v - __bfloat162float(h));
}

// ---------------------------------------------------------------------------
// Split-bf16 tensor-core GEMM.
//   C = alpha * (Ah+Al) @ (Bh+Bl)^T   (drops Al*Bl term; ~2^-16 rel err)
// A arrays: row-major [M][lda] bf16, k-contiguous.
// B arrays: row-major [N][ldb] bf16, k-contiguous  (i.e. op(B) = B^T).
// EPI=0: write fp32 Cf (+ optional bias). EPI=1: write bf16 hi/lo pair.
// Batched via blockIdx.z: offset = (z/inner)*s?o + (z%inner)*s?i (elements).
// ---------------------------------------------------------------------------
template <int BM, int BN, int BK, int WM, int WN, int EPI>
__global__ void __launch_bounds__(256)
mma_gemm(const __nv_bfloat16* __restrict__ Ah, const __nv_bfloat16* __restrict__ Al,
         const __nv_bfloat16* __restrict__ Bh, const __nv_bfloat16* __restrict__ Bl,
         float* __restrict__ Cf, const float* __restrict__ bias,
         __nv_bfloat16* __restrict__ Ch, __nv_bfloat16* __restrict__ Cl,
         int K, int lda, int ldb, int ldc,
         long sAi, long sAo, long sBi, long sBo, long sCi, long sCo,
         int innerCount, float alpha)
{
    constexpr int THREADS = 256;
    constexpr int BKP = BK + 8;                 // +16B pad: conflict-free LDSM
    constexpr int A_TILE = BM * BKP;
    constexpr int B_TILE = BN * BKP;
    constexpr int STAGE = 2 * A_TILE + 2 * B_TILE;
    constexpr int WARPS_N = BN / WN;
    constexpr int MT = WM / 16, NT = WN / 8;
    extern __shared__ __nv_bfloat16 smem[];

    const int z  = blockIdx.z;
    const int zo = z / innerCount;
    const int zi = z % innerCount;
    const long aofs = (long)zo * sAo + (long)zi * sAi;
    const long bofs = (long)zo * sBo + (long)zi * sBi;
    const long cofs = (long)zo * sCo + (long)zi * sCi;
    Ah += aofs; Al += aofs;
    Bh += bofs; Bl += bofs;

    const int m0 = blockIdx.y * BM;
    const int n0 = blockIdx.x * BN;
    const int tid = threadIdx.x;
    const int lane = tid & 31;
    const int wid = tid >> 5;
    const int wm0 = (wid / WARPS_N) * WM;
    const int wn0 = (wid % WARPS_N) * WN;

    float acc[MT][NT][4];
#pragma unroll
    for (int i = 0; i < MT; i++)
#pragma unroll
        for (int j = 0; j < NT; j++)
#pragma unroll
            for (int c = 0; c < 4; c++) acc[i][j][c] = 0.0f;

    auto load_stage = [&](int st, int k0) {
        __nv_bfloat16* s = smem + st * STAGE;
#pragma unroll
        for (int it = 0; it < (BM * BK / 8) / THREADS; it++) {
            int c = tid + it * THREADS;
            int row = c / (BK / 8);
            int col = (c % (BK / 8)) * 8;
            long go = (long)(m0 + row) * lda + k0 + col;
            cp16(&s[row * BKP + col], Ah + go);
            cp16(&s[A_TILE + row * BKP + col], Al + go);
        }
#pragma unroll
        for (int it = 0; it < (BN * BK / 8) / THREADS; it++) {
            int c = tid + it * THREADS;
            int row = c / (BK / 8);
            int col = (c % (BK / 8)) * 8;
            long go = (long)(n0 + row) * ldb + k0 + col;
            cp16(&s[2 * A_TILE + row * BKP + col], Bh + go);
            cp16(&s[2 * A_TILE + B_TILE + row * BKP + col], Bl + go);
        }
    };

    const int iters = K / BK;
    load_stage(0, 0);
    CP_COMMIT;
    CP_WAIT0;
    __syncthreads();

    for (int kb = 0; kb < iters; kb++) {
        const int cur = kb & 1;
        if (kb + 1 < iters) { load_stage(cur ^ 1, (kb + 1) * BK); CP_COMMIT; }

        const __nv_bfloat16* s = smem + cur * STAGE;
#pragma unroll
        for (int ks = 0; ks < BK / 16; ks++) {
            uint32_t a_h[MT][4], a_l[MT][4], b_h[NT][2], b_l[NT][2];
#pragma unroll
            for (int i = 0; i < MT; i++) {
                int row = wm0 + i * 16 + (lane & 15);
                int col = ks * 16 + ((lane >> 4) << 3);
                const __nv_bfloat16* pa = s + row * BKP + col;
                ldsm_x4(a_h[i], smem_u32(pa));
                ldsm_x4(a_l[i], smem_u32(pa + A_TILE));
            }
#pragma unroll
            for (int j = 0; j < NT; j += 2) {
                int r = lane & 7, gg = lane >> 3;
                int row = wn0 + (j + (gg >> 1)) * 8 + r;
                int col = ks * 16 + (gg & 1) * 8;
                const __nv_bfloat16* pb = s + 2 * A_TILE + row * BKP + col;
                uint32_t t4[4];
                ldsm_x4(t4, smem_u32(pb));
                b_h[j][0] = t4[0]; b_h[j][1] = t4[1];
                b_h[j + 1][0] = t4[2]; b_h[j + 1][1] = t4[3];
                ldsm_x4(t4, smem_u32(pb + B_TILE));
                b_l[j][0] = t4[0]; b_l[j][1] = t4[1];
                b_l[j + 1][0] = t4[2]; b_l[j + 1][1] = t4[3];
            }
#pragma unroll
            for (int i = 0; i < MT; i++)
#pragma unroll
                for (int j = 0; j < NT; j++) {
                    mma16816(acc[i][j], a_h[i], b_h[j]);
                    mma16816(acc[i][j], a_h[i], b_l[j]);
                    mma16816(acc[i][j], a_l[i], b_h[j]);
                }
        }
        CP_WAIT0;
        __syncthreads();
    }

    // ---- epilogue ----
    const int gg = lane >> 2, tt = lane & 3;
#pragma unroll
    for (int i = 0; i < MT; i++)
#pragma unroll
        for (int j = 0; j < NT; j++) {
            long m = m0 + wm0 + i * 16 + gg;
            int  n = n0 + wn0 + j * 8 + tt * 2;
            if (EPI == 0) {
                float b0 = 0.f, b1 = 0.f;
                if (bias != nullptr) { b0 = bias[n]; b1 = bias[n + 1]; }
                float2 v0 = make_float2(alpha * acc[i][j][0] + b0,
                                        alpha * acc[i][j][1] + b1);
                float2 v1 = make_float2(alpha * acc[i][j][2] + b0,
                                        alpha * acc[i][j][3] + b1);
                *reinterpret_cast<float2*>(&Cf[cofs + m * ldc + n])       = v0;
                *reinterpret_cast<float2*>(&Cf[cofs + (m + 8) * ldc + n]) = v1;
            } else {
                __nv_bfloat16 h, l;
                __nv_bfloat162 vh, vl;
                split2(acc[i][j][0], h, l); vh.x = h; vl.x = l;
                split2(acc[i][j][1], h, l); vh.y = h; vl.y = l;
                *reinterpret_cast<__nv_bfloat162*>(&Ch[cofs + m * ldc + n]) = vh;
                *reinterpret_cast<__nv_bfloat162*>(&Cl[cofs + m * ldc + n]) = vl;
                split2(acc[i][j][2], h, l); vh.x = h; vl.x = l;
                split2(acc[i][j][3], h, l); vh.y = h; vl.y = l;
                *reinterpret_cast<__nv_bfloat162*>(&Ch[cofs + (m + 8) * ldc + n]) = vh;
                *reinterpret_cast<__nv_bfloat162*>(&Cl[cofs + (m + 8) * ldc + n]) = vl;
            }
        }
}

// ---------------------------------------------------------------------------
// Elementwise fp32 -> bf16 hi/lo split (x). 4 elems/thread.
// ---------------------------------------------------------------------------
__global__ void split_x_k(const float* __restrict__ x,
                          __nv_bfloat16* __restrict__ oh,
                          __nv_bfloat16* __restrict__ ol)
{
    long i = ((long)blockIdx.x * blockDim.x + threadIdx.x) * 4;
    float4 v = *reinterpret_cast<const float4*>(x + i);
    __nv_bfloat16 h, l;
    __nv_bfloat162 h0, l0, h1, l1;
    split2(v.x, h, l); h0.x = h; l0.x = l;
    split2(v.y, h, l); h0.y = h; l0.y = l;
    split2(v.z, h, l); h1.x = h; l1.x = l;
    split2(v.w, h, l); h1.y = h; l1.y = l;
    *reinterpret_cast<__nv_bfloat162*>(oh + i)     = h0;
    *reinterpret_cast<__nv_bfloat162*>(oh + i + 2) = h1;
    *reinterpret_cast<__nv_bfloat162*>(ol + i)     = l0;
    *reinterpret_cast<__nv_bfloat162*>(ol + i + 2) = l1;
}

// ---------------------------------------------------------------------------
// Transpose + split: W fp32 [K][N] -> T_hi/T_lo bf16 [N][K]. block (32,8).
// ---------------------------------------------------------------------------
__global__ void tsplit_k(const float* __restrict__ W,
                         __nv_bfloat16* __restrict__ Th,
                         __nv_bfloat16* __restrict__ Tl, int Kd, int Nd)
{
    __shared__ float tile[32][33];
    const int n0 = blockIdx.x * 32, k0 = blockIdx.y * 32;
    const int tx = threadIdx.x, ty = threadIdx.y;
    for (int i = ty; i < 32; i += 8)
        tile[i][tx] = W[(long)(k0 + i) * Nd + n0 + tx];
    __syncthreads();
    for (int i = ty; i < 32; i += 8) {
        float v = tile[tx][i];
        __nv_bfloat16 h, l;
        split2(v, h, l);
        Th[(long)(n0 + i) * Kd + k0 + tx] = h;
        Tl[(long)(n0 + i) * Kd + k0 + tx] = l;
    }
}

// ---------------------------------------------------------------------------
// Transpose V (bf16 hi/lo) out of qkv into vT [bh][64][1024]. block (32,8).
// ---------------------------------------------------------------------------
__global__ void vtrans_k(const __nv_bfloat16* __restrict__ Qh,
                         const __nv_bfloat16* __restrict__ Ql,
                         __nv_bfloat16* __restrict__ VTh,
                         __nv_bfloat16* __restrict__ VTl)
{
    __shared__ __nv_bfloat16 th[32][33], tl[32][33];
    const int t0 = blockIdx.x * 32;            // token
    const int d0 = blockIdx.y * 32;            // head dim
    const int z  = blockIdx.z;                 // b*16+h
    const int b = z >> 4, h = z & 15;
    const int tx = threadIdx.x, ty = threadIdx.y;
    const long src = (long)b * N_DIM * 3 * C_DIM + 2 * C_DIM + h * HD;
    for (int i = ty; i < 32; i += 8) {
        long o = src + (long)(t0 + i) * (3 * C_DIM) + d0 + tx;
        th[i][tx] = Qh[o];
        tl[i][tx] = Ql[o];
    }
    __syncthreads();
    const long dst = (long)z * HD * N_DIM;
    for (int i = ty; i < 32; i += 8) {
        long o = dst + (long)(d0 + i) * N_DIM + t0 + tx;
        VTh[o] = th[tx][i];
        VTl[o] = tl[tx][i];
    }
}

// ---------------------------------------------------------------------------
// Row softmax over 1024 floats, in place; also emits bf16 hi/lo copies.
// ---------------------------------------------------------------------------
__global__ void softmax1024(float* __restrict__ data,
                            __nv_bfloat16* __restrict__ oh,
                            __nv_bfloat16* __restrict__ ol)
{
    const long row = blockIdx.x;
    float4* p = reinterpret_cast<float4*>(data + row * 1024);
    const int t = threadIdx.x, warp = t >> 5, lane = t & 31;

    float4 v = p[t];
    float m = fmaxf(fmaxf(v.x, v.y), fmaxf(v.z, v.w));
#pragma unroll
    for (int o = 16; o > 0; o >>= 1)
        m = fmaxf(m, __shfl_xor_sync(0xffffffffu, m, o));

    __shared__ float red[8];
    if (lane == 0) red[warp] = m;
    __syncthreads();
    float M = red[0];
#pragma unroll
    for (int i = 1; i < 8; i++) M = fmaxf(M, red[i]);

    v.x = expf(v.x - M); v.y = expf(v.y - M);
    v.z = expf(v.z - M); v.w = expf(v.w - M);
    float s = v.x + v.y + v.z + v.w;
#pragma unroll
    for (int o = 16; o > 0; o >>= 1)
        s += __shfl_xor_sync(0xffffffffu, s, o);

    __syncthreads();
    if (lane == 0) red[warp] = s;
    __syncthreads();
    float S = red[0];
#pragma unroll
    for (int i = 1; i < 8; i++) S += red[i];

    const float r = 1.0f / S;
    v.x *= r; v.y *= r; v.z *= r; v.w *= r;
    p[t] = v;

    __nv_bfloat16 h, l;
    __nv_bfloat162 h0, l0, h1, l1;
    split2(v.x, h, l); h0.x = h; l0.x = l;
    split2(v.y, h, l); h0.y = h; l0.y = l;
    split2(v.z, h, l); h1.x = h; l1.x = l;
    split2(v.w, h, l); h1.y = h; l1.y = l;
    __nv_bfloat162* ph = reinterpret_cast<__nv_bfloat162*>(oh + row * 1024);
    __nv_bfloat162* pl = reinterpret_cast<__nv_bfloat162*>(ol + row * 1024);
    ph[2 * t] = h0; ph[2 * t + 1] = h1;
    pl[2 * t] = l0; pl[2 * t + 1] = l1;
}

// ---------------------------------------------------------------------------
// kernel_launch
// ---------------------------------------------------------------------------
extern "C" void kernel_launch(void* const* d_in, const int* in_sizes, int n_in,
                              void* d_out, int out_size)
{
    const float* x      = (const float*)d_in[0];
    const float* w_qkv  = (const float*)d_in[1];
    const float* w_proj = (const float*)d_in[2];
    const float* b_proj = (const float*)d_in[3];
    float* out = (float*)d_out;

    __nv_bfloat16 *x_hi, *x_lo, *wqT_hi, *wqT_lo, *wpT_hi, *wpT_lo;
    __nv_bfloat16 *qkv_hi, *qkv_lo, *vT_hi, *vT_lo;
    __nv_bfloat16 *attn_hi, *attn_lo, *ctx_hi, *ctx_lo;
    float* attn_scratch;
    cudaGetSymbolAddress((void**)&x_hi, g_x_hi);
    cudaGetSymbolAddress((void**)&x_lo, g_x_lo);
    cudaGetSymbolAddress((void**)&wqT_hi, g_wqkvT_hi);
    cudaGetSymbolAddress((void**)&wqT_lo, g_wqkvT_lo);
    cudaGetSymbolAddress((void**)&wpT_hi, g_wprojT_hi);
    cudaGetSymbolAddress((void**)&wpT_lo, g_wprojT_lo);
    cudaGetSymbolAddress((void**)&qkv_hi, g_qkv_hi);
    cudaGetSymbolAddress((void**)&qkv_lo, g_qkv_lo);
    cudaGetSymbolAddress((void**)&vT_hi, g_vT_hi);
    cudaGetSymbolAddress((void**)&vT_lo, g_vT_lo);
    cudaGetSymbolAddress((void**)&attn_hi, g_attn_hi);
    cudaGetSymbolAddress((void**)&attn_lo, g_attn_lo);
    cudaGetSymbolAddress((void**)&ctx_hi, g_ctx_hi);
    cudaGetSymbolAddress((void**)&ctx_lo, g_ctx_lo);
    cudaGetSymbolAddress((void**)&attn_scratch, g_attn);

    const long OUT_ELEMS  = (long)B_DIM * N_DIM * C_DIM;
    const long ATTN_ELEMS = (long)B_DIM * H_DIM * N_DIM * N_DIM;
    float* attn = ((long)out_size >= OUT_ELEMS + ATTN_ELEMS) ? (out + OUT_ELEMS)
                                                             : attn_scratch;

    // dynamic smem opt-in for the GEMM instantiations (>48KB)
    constexpr int SM128 = 2 * (2 * 128 * 40 + 2 * 128 * 40) * 2;  // 81920 B
    constexpr int SM64  = 2 * (2 * 128 * 40 + 2 * 64 * 40) * 2;   // 61440 B
    cudaFuncSetAttribute(mma_gemm<128, 128, 32, 64, 32, 0>,
                         cudaFuncAttributeMaxDynamicSharedMemorySize, SM128);
    cudaFuncSetAttribute(mma_gemm<128, 128, 32, 64, 32, 1>,
                         cudaFuncAttributeMaxDynamicSharedMemorySize, SM128);
    cudaFuncSetAttribute(mma_gemm<128, 64, 32, 32, 32, 1>,
                         cudaFuncAttributeMaxDynamicSharedMemorySize, SM64);

    // 0) split inputs / transpose weights
    split_x_k<<<8192, 256>>>(x, x_hi, x_lo);
    tsplit_k<<<dim3(3 * C_DIM / 32, C_DIM / 32), dim3(32, 8)>>>(
        w_qkv, wqT_hi, wqT_lo, C_DIM, 3 * C_DIM);
    tsplit_k<<<dim3(C_DIM / 32, C_DIM / 32), dim3(32, 8)>>>(
        w_proj, wpT_hi, wpT_lo, C_DIM, C_DIM);

    // 1) qkv = x @ w_qkv  -> bf16 hi/lo  [8192 x 3072]
    mma_gemm<128, 128, 32, 64, 32, 1><<<dim3(24, 64, 1), 256, SM128>>>(
        x_hi, x_lo, wqT_hi, wqT_lo,
        nullptr, nullptr, qkv_hi, qkv_lo,
        C_DIM, C_DIM, C_DIM, 3 * C_DIM,
        0, 0, 0, 0, 0, 0, 1, 1.0f);

    // 1b) transpose V into [bh][64][1024]
    vtrans_k<<<dim3(32, 2, 128), dim3(32, 8)>>>(qkv_hi, qkv_lo, vT_hi, vT_lo);

    // 2) scores = scale * Q @ K^T  per (b,h)  -> fp32 attn buffer
    mma_gemm<128, 128, 32, 64, 32, 0><<<dim3(8, 8, 128), 256, SM128>>>(
        qkv_hi, qkv_lo, qkv_hi + C_DIM, qkv_lo + C_DIM,
        attn, nullptr, nullptr, nullptr,
        HD, 3 * C_DIM, 3 * C_DIM, N_DIM,
        /*A:*/ (long)HD, (long)N_DIM * 3 * C_DIM,
        /*B:*/ (long)HD, (long)N_DIM * 3 * C_DIM,
        /*C:*/ (long)N_DIM * N_DIM, (long)H_DIM * N_DIM * N_DIM,
        H_DIM, 0.125f);

    // 3) softmax (in place) + emit bf16 hi/lo attn
    softmax1024<<<B_DIM * H_DIM * N_DIM, 256>>>(attn, attn_hi, attn_lo);

    // 4) ctx = attn @ V  per (b,h)  -> bf16 hi/lo ctx [8192 x 1024]
    mma_gemm<128, 64, 32, 32, 32, 1><<<dim3(1, 8, 128), 256, SM64>>>(
        attn_hi, attn_lo, vT_hi, vT_lo,
        nullptr, nullptr, ctx_hi, ctx_lo,
        N_DIM, N_DIM, N_DIM, C_DIM,
        /*A:*/ (long)N_DIM * N_DIM, (long)H_DIM * N_DIM * N_DIM,
        /*B:*/ (long)HD * N_DIM, (long)H_DIM * HD * N_DIM,
        /*C:*/ (long)HD, (long)N_DIM * C_DIM,
        H_DIM, 1.0f);

    // 5) out = ctx @ w_proj + b_proj  -> fp32
    mma_gemm<128, 128, 32, 64, 32, 0><<<dim3(8, 64, 1), 256, SM128>>>(
        ctx_hi, ctx_lo, wpT_hi, wpT_lo,
        out, b_proj, nullptr, nullptr,
        C_DIM, C_DIM, C_DIM, C_DIM,
        0, 0, 0, 0, 0, 0, 1, 1.0f);
}